// round 16
// baseline (speedup 1.0000x reference)
#include <cuda_runtime.h>
#include <cuda_bf16.h>
#include <math.h>
#include <stdint.h>

#define B_  2
#define T_  2048
#define E_  1024
#define H_  16
#define HD_ 64
#define M_  (B_*T_)
#define NT_ (T_/64)

#define TSTRIDE 80
#define TILE_BYTES (128*TSTRIDE)
#define BUF_BYTES (4*TILE_BYTES)     // 40960
#define DYN_SMEM (2*BUF_BYTES)       // 81920 -> 2 CTAs/SM

// ---------------- scratch ----------------
__device__ float g_Q[B_*H_*T_*HD_];
__device__ float g_K[B_*H_*T_*HD_];
__device__ float g_V[B_*H_*T_*HD_];
__device__ float g_G[B_*T_*E_];
__device__ float g_O[B_*T_*E_];
__device__ float g_decay[H_*T_];
__device__ float g_R[B_*H_*NT_*HD_*HD_];
__device__ float g_U[B_*H_*NT_*HD_*HD_];
__device__ float4 g_rope[T_*32];
__device__ float2 g_stat[B_*H_];
__device__ __nv_bfloat16 g_Ah[M_*E_], g_Al[M_*E_];
__device__ __nv_bfloat16 g_Wh[5*E_*E_], g_Wl[5*E_*E_];

// ---------------- helpers ----------------
__device__ __forceinline__ uint32_t smem_u32(const void* p){
    uint32_t a; asm("{ .reg .u64 t; cvta.to.shared.u64 t, %1; cvt.u32.u64 %0, t; }":"=r"(a):"l"(p)); return a;
}
__device__ __forceinline__ void ldsm4(uint32_t r[4], uint32_t a){
    asm volatile("ldmatrix.sync.aligned.m8n8.x4.shared.b16 {%0,%1,%2,%3}, [%4];"
        :"=r"(r[0]),"=r"(r[1]),"=r"(r[2]),"=r"(r[3]):"r"(a));
}
__device__ __forceinline__ void mma16816(float c[4], const uint32_t a[4], const uint32_t b[2]){
    asm volatile("mma.sync.aligned.m16n8k16.row.col.f32.bf16.bf16.f32 "
        "{%0,%1,%2,%3}, {%4,%5,%6,%7}, {%8,%9}, {%0,%1,%2,%3};"
        : "+f"(c[0]),"+f"(c[1]),"+f"(c[2]),"+f"(c[3])
        : "r"(a[0]),"r"(a[1]),"r"(a[2]),"r"(a[3]),"r"(b[0]),"r"(b[1]));
}
#define CPA16(dst, src)  asm volatile("cp.async.cg.shared.global [%0], [%1], 16;"::"r"(dst),"l"(src))
#define CPA_COMMIT()     asm volatile("cp.async.commit_group;":::"memory")
#define CPA_WAIT1()      asm volatile("cp.async.wait_group 1;":::"memory")
#define CPA_WAIT0()      asm volatile("cp.async.wait_group 0;":::"memory")

// ---------------- prep: split + decay/rope tables + stat zero (R12 scalar version) ----------------
__global__ void split_all_kernel(const float* __restrict__ x,
    const float* __restrict__ Wq, const float* __restrict__ Wk,
    const float* __restrict__ Wv, const float* __restrict__ Wg,
    const float* __restrict__ Wo)
{
    const int i = blockIdx.x*256 + threadIdx.x;
    if (i < B_*H_) g_stat[i] = make_float2(0.f, 0.f);
    if (i < H_*T_) {
        const int h = i >> 11, d = i & 2047;
        const double gamma = 1.0 - exp2(-(double)(5 + h));
        g_decay[i] = (float)pow(gamma, (double)d);
    }
    if (i < T_*32) {
        const int t = i >> 5, p = i & 31;
        float inv0 = (float)pow(10000.0, -(double)((2*p)   & 31) / 32.0);
        float inv1 = (float)pow(10000.0, -(double)((2*p+1) & 31) / 32.0);
        float s0,c0,s1,c1;
        sincosf((float)t * inv0, &s0, &c0);
        sincosf((float)t * inv1, &s1, &c1);
        g_rope[i] = make_float4(c0, s0, c1, s1);
    }
    const int NX = M_*E_;
    const int NTOT = NX + 5*E_*E_;
    if (i >= NTOT) return;
    float v; __nv_bfloat16 *hi, *lo;
    if (i < NX) {
        v = x[i]; hi = g_Ah + i; lo = g_Al + i;
    } else {
        const int j = i - NX;
        const int w = j >> 20, off = j & ((1<<20)-1);
        const float* src = (w==0)?Wq:(w==1)?Wk:(w==2)?Wv:(w==3)?Wg:Wo;
        v = src[off]; hi = g_Wh + j; lo = g_Wl + j;
    }
    const __nv_bfloat16 h = __float2bfloat16(v);
    *hi = h; *lo = __float2bfloat16(v - __bfloat162float(h));
}

// ---------------- HMMA GEMM 128x128 tile, bf16 3-term split, 2 CTAs/SM ----------------
// MODE 0: z = blockIdx.z in {Q,K,V,G}; A tiles from g_Ah/g_Al via cp.async.
// MODE 1: Wo GEMM; A tiles computed on the fly: ((O-mu)*rs*w + b)*G, split hi/lo.
template<int MODE>
__global__ __launch_bounds__(256, 2) void tc_gemm(
    const __nv_bfloat16* __restrict__ Ah, const __nv_bfloat16* __restrict__ Al,
    const float* __restrict__ b0, const float* __restrict__ b1,
    const float* __restrict__ b2, const float* __restrict__ b3,
    float* __restrict__ Cout)
{
    extern __shared__ __align__(16) char smem[];
    const int z = (MODE == 1) ? 4 : blockIdx.z;
    const float* bias = (z==1) ? b1 : (z==2) ? b2 : (z==3) ? b3 : b0;
    const __nv_bfloat16* Wh = g_Wh + (size_t)z * (E_*E_);
    const __nv_bfloat16* Wl = g_Wl + (size_t)z * (E_*E_);
    const int bm = blockIdx.y * 128, bn = blockIdx.x * 128;
    const int tid = threadIdx.x, wid = tid >> 5, lane = tid & 31;
    const int warp_m = wid >> 2, warp_n = wid & 3;
    const uint32_t sbase = smem_u32(smem);
    // MODE 1: gn params arrive via b1 (gn_w) and b2 (gn_b)
    const float* gnw = b1;
    const float* gnb = b2;
    const float INVN = 1.f / (float)(T_ * HD_);

    float c[4][4][4];
    #pragma unroll
    for (int i = 0; i < 4; ++i)
        #pragma unroll
        for (int j = 0; j < 4; ++j)
            #pragma unroll
            for (int r = 0; r < 4; ++r) c[i][j][r] = 0.f;

    const char* srcp[8];
    uint32_t dsto[8];
    #pragma unroll
    for (int q = 0; q < 8; ++q) {
        const int ch = tid + q*256;
        const int tile = ch >> 9, row = (ch & 511) >> 2, seg = (ch & 3) * 16;
        const __nv_bfloat16* base = (tile==0)?Ah:(tile==1)?Al:(tile==2)?Wh:Wl;
        const int rowbase = (tile < 2) ? bm : bn;
        srcp[q] = (const char*)(base + (size_t)(rowbase + row)*E_) + seg;
        dsto[q] = (uint32_t)(tile*TILE_BYTES + row*TSTRIDE + seg);
    }

    auto issue = [&](int s) {
        char* dstbuf = smem + (size_t)(s & 1)*BUF_BYTES;
        const uint32_t dstbuf_u = sbase + (uint32_t)(s & 1)*BUF_BYTES;
        const size_t soff = (size_t)s*64;
        if (MODE == 1) {
            // A tiles: fused GroupNorm + gate + bf16 split (q = 0,1 cover tile0's 512 chunks)
            #pragma unroll
            for (int q = 0; q < 2; ++q) {
                const int ch = tid + q*256;            // 0..511
                const int row = ch >> 2;               // 0..127
                const int eoff = (ch & 3) * 8;         // 0,8,16,24
                const int m = bm + row;
                const int col = s*32 + eoff;
                const int bh = (m >> 11)*H_ + (col >> 6);
                const float2 st = g_stat[bh];
                const float mu = st.x * INVN;
                const float rs = rsqrtf(st.y * INVN - mu*mu + 1e-5f);
                const float* Og = g_O + (size_t)m*E_ + col;
                const float* Gg = g_G + (size_t)m*E_ + col;
                float ov[8], gv[8], wv[8], bv[8];
                *(float4*)&ov[0] = *(const float4*)Og;       *(float4*)&ov[4] = *(const float4*)(Og+4);
                *(float4*)&gv[0] = *(const float4*)Gg;       *(float4*)&gv[4] = *(const float4*)(Gg+4);
                *(float4*)&wv[0] = *(const float4*)(gnw+col); *(float4*)&wv[4] = *(const float4*)(gnw+col+4);
                *(float4*)&bv[0] = *(const float4*)(gnb+col); *(float4*)&bv[4] = *(const float4*)(gnb+col+4);
                __nv_bfloat16 hi8[8], lo8[8];
                #pragma unroll
                for (int e = 0; e < 8; ++e) {
                    const float out = ((ov[e] - mu) * rs * wv[e] + bv[e]) * gv[e];
                    hi8[e] = __float2bfloat16(out);
                    lo8[e] = __float2bfloat16(out - __bfloat162float(hi8[e]));
                }
                char* dA = dstbuf + row*TSTRIDE + (ch & 3)*16;
                *(uint4*)dA                 = *(uint4*)hi8;
                *(uint4*)(dA + TILE_BYTES)  = *(uint4*)lo8;
            }
            // W tiles via cp.async (q = 4..7)
            #pragma unroll
            for (int q = 4; q < 8; ++q) CPA16(dstbuf_u + dsto[q], srcp[q] + soff);
            CPA_COMMIT();
        } else {
            #pragma unroll
            for (int q = 0; q < 8; ++q) CPA16(dstbuf_u + dsto[q], srcp[q] + soff);
            CPA_COMMIT();
        }
    };

    issue(0); issue(1);
    const int lrow15 = lane & 15;
    const uint32_t kseg = (lane >> 4) * 16;

    uint32_t a_off[4], b_off[2];
    #pragma unroll
    for (int mf = 0; mf < 4; ++mf)
        a_off[mf] = (uint32_t)((warp_m*64 + mf*16 + lrow15) * TSTRIDE) + kseg;
    #pragma unroll
    for (int p = 0; p < 2; ++p)
        b_off[p] = (uint32_t)((warp_n*32 + p*16 + lrow15) * TSTRIDE) + kseg + 2*TILE_BYTES;

    for (int s = 0; s < 32; ++s) {
        if (s < 31) CPA_WAIT1(); else CPA_WAIT0();
        __syncthreads();
        const uint32_t buf = sbase + (uint32_t)(s & 1)*BUF_BYTES;

        uint32_t bh[2][4][2], bl[2][4][2];
        #pragma unroll
        for (int k16 = 0; k16 < 2; ++k16) {
            const uint32_t koff = buf + k16*32;
            #pragma unroll
            for (int p = 0; p < 2; ++p) {
                uint32_t r[4];
                ldsm4(r, koff + b_off[p]);
                bh[k16][2*p][0]=r[0]; bh[k16][2*p][1]=r[2];
                bh[k16][2*p+1][0]=r[1]; bh[k16][2*p+1][1]=r[3];
                ldsm4(r, koff + b_off[p] + TILE_BYTES);
                bl[k16][2*p][0]=r[0]; bl[k16][2*p][1]=r[2];
                bl[k16][2*p+1][0]=r[1]; bl[k16][2*p+1][1]=r[3];
            }
        }
        #pragma unroll
        for (int k16 = 0; k16 < 2; ++k16) {
            const uint32_t koff = buf + k16*32;
            #pragma unroll
            for (int mf = 0; mf < 4; ++mf) {
                uint32_t ah[4], al[4];
                ldsm4(ah, koff + a_off[mf]);
                ldsm4(al, koff + a_off[mf] + TILE_BYTES);
                #pragma unroll
                for (int nf = 0; nf < 4; ++nf) {
                    mma16816(c[mf][nf], ah, bh[k16][nf]);
                    mma16816(c[mf][nf], ah, bl[k16][nf]);
                    mma16816(c[mf][nf], al, bh[k16][nf]);
                }
            }
        }
        __syncthreads();
        if (s + 2 < 32) issue(s + 2);
    }

    const int tq = lane >> 2, tr = lane & 3;
    #pragma unroll
    for (int mf = 0; mf < 4; ++mf) {
        #pragma unroll
        for (int nf = 0; nf < 4; ++nf) {
            #pragma unroll
            for (int half = 0; half < 2; ++half) {
                const int m = bm + warp_m*64 + mf*16 + tq + half*8;
                const int n0 = bn + warp_n*32 + nf*8 + tr*2;
                float v0 = c[mf][nf][half*2 + 0] + bias[n0];
                float v1 = c[mf][nf][half*2 + 1] + bias[n0 + 1];
                const int bb = m >> 11, t = m & 2047;
                if (MODE == 1) {
                    *(float2*)(Cout + (size_t)m*E_ + n0) = make_float2(v0, v1);
                } else if (z <= 2) {
                    const int h = n0 >> 6, hd = n0 & 63;
                    float* dst = ((z==0) ? g_Q : (z==1) ? g_K : g_V)
                                 + (((size_t)(bb*H_ + h) * T_ + t) * HD_) + hd;
                    if (z <= 1) {
                        const float4 cs = g_rope[(size_t)t*32 + (hd >> 1)];
                        *(float2*)dst = make_float2(v0*cs.x - v1*cs.y, v1*cs.z + v0*cs.w);
                    } else {
                        *(float2*)dst = make_float2(v0, v1);
                    }
                } else {
                    g_G[(size_t)m*E_ + n0]     = v0 / (1.f + __expf(-v0));
                    g_G[(size_t)m*E_ + n0 + 1] = v1 / (1.f + __expf(-v1));
                }
            }
        }
    }
}

// ---------------- Pass 1a: per-chunk outer products ----------------
__global__ __launch_bounds__(256) void ret_u_kernel()
{
    __shared__ float KT[64][64];
    __shared__ float Vs[64][64];

    const int cc = blockIdx.x + 1;
    const int bh = blockIdx.y, h = bh & 15;
    const int j0 = cc * 64;
    const float* dec = g_decay + h * T_;

    const float* Kg = g_K + (size_t)bh * T_ * HD_;
    const float* Vg = g_V + (size_t)bh * T_ * HD_;
    float* Ug = g_U + ((size_t)bh * NT_ + cc) * (HD_*HD_);

    const int tid = threadIdx.x;
    const int tx = tid & 15, ty = tid >> 4;
    const int lrow = tid >> 2, lseg = (tid & 3) * 16;

    {
        const float w = dec[lrow];
        float4 k4[4];
        const float4* ks = (const float4*)(Kg + (size_t)(j0+lrow)*64 + lseg);
        #pragma unroll
        for (int q = 0; q < 4; ++q) k4[q] = ks[q];
        #pragma unroll
        for (int q = 0; q < 4; ++q) {
            KT[lseg+q*4+0][lrow] = k4[q].x * w;
            KT[lseg+q*4+1][lrow] = k4[q].y * w;
            KT[lseg+q*4+2][lrow] = k4[q].z * w;
            KT[lseg+q*4+3][lrow] = k4[q].w * w;
        }
        const float4* vs = (const float4*)(Vg + (size_t)(j0+lrow)*64 + lseg);
        float4* vd = (float4*)(&Vs[lrow][lseg]);
        #pragma unroll
        for (int q = 0; q < 4; ++q) vd[q] = vs[q];
    }
    __syncthreads();

    float u[4][4];
    #pragma unroll
    for (int i = 0; i < 4; ++i)
        #pragma unroll
        for (int j = 0; j < 4; ++j) u[i][j] = 0.f;

    #pragma unroll 8
    for (int t = 0; t < 64; ++t) {
        float4 vv = *(const float4*)(&Vs[t][tx*4]);
        float kd[4];
        #pragma unroll
        for (int i = 0; i < 4; ++i) kd[i] = KT[ty*4+i][t];
        #pragma unroll
        for (int i = 0; i < 4; ++i) {
            u[i][0] = fmaf(kd[i], vv.x, u[i][0]); u[i][1] = fmaf(kd[i], vv.y, u[i][1]);
            u[i][2] = fmaf(kd[i], vv.z, u[i][2]); u[i][3] = fmaf(kd[i], vv.w, u[i][3]);
        }
    }
    #pragma unroll
    for (int i = 0; i < 4; ++i)
        *(float4*)&Ug[(ty*4+i)*64 + tx*4] = make_float4(u[i][0], u[i][1], u[i][2], u[i][3]);
}

// ---------------- Pass 1b: elementwise backward scan (float2) ----------------
__global__ __launch_bounds__(256) void ret_scan_kernel()
{
    const int idx = blockIdx.x*256 + threadIdx.x;       // 0..65535
    const int bh = idx >> 11;
    const int de = (idx & 2047) * 2;
    const float gL = g_decay[(bh & 15)*T_ + 64];

    float* Rg = g_R + (size_t)bh * NT_ * (HD_*HD_) + de;
    const float* Ug = g_U + (size_t)bh * NT_ * (HD_*HD_) + de;

    float2 R = make_float2(0.f, 0.f);
    *(float2*)(Rg + (NT_-1)*(HD_*HD_)) = R;
    #pragma unroll 4
    for (int cc = NT_-1; cc >= 1; --cc) {
        const float2 U = *(const float2*)(Ug + cc*(HD_*HD_));
        R.x = U.x + gL*R.x; R.y = U.y + gL*R.y;
        *(float2*)(Rg + (cc-1)*(HD_*HD_)) = R;
    }
}

// ---------------- Pass 2: intra + cross chunk, fused GroupNorm stats ----------------
__global__ __launch_bounds__(256) void ret_attn_kernel()
{
    __shared__ float Qs[64][64];
    __shared__ float KS[64][64];
    __shared__ float Vs[64][64];

    const int bh = blockIdx.y, b = bh >> 4, h = bh & 15;
    const int cI = blockIdx.x, q0 = cI * 64;

    const float* Qg = g_Q + (size_t)bh * T_ * HD_;
    const float* Kg = g_K + (size_t)bh * T_ * HD_;
    const float* Vg = g_V + (size_t)bh * T_ * HD_;
    const float* dec = g_decay + h * T_;
    const float* Rg = g_R + ((size_t)bh * NT_ + cI) * (HD_*HD_);

    const int tid = threadIdx.x;
    const int tx = tid & 15, ty = tid >> 4;
    const int lrow = tid >> 2, lseg = (tid & 3) * 16;

    {
        const float4* qsrc = (const float4*)(Qg + (size_t)(q0+lrow)*64 + lseg);
        float4* qdst = (float4*)(&Qs[lrow][lseg]);
        #pragma unroll
        for (int q = 0; q < 4; ++q) qdst[q] = qsrc[q];
        float4 k4[4];
        const float4* ks = (const float4*)(Kg + (size_t)(q0+lrow)*64 + lseg);
        #pragma unroll
        for (int q = 0; q < 4; ++q) k4[q] = ks[q];
        #pragma unroll
        for (int q = 0; q < 4; ++q) {
            KS[lseg+q*4+0][lrow] = k4[q].x; KS[lseg+q*4+1][lrow] = k4[q].y;
            KS[lseg+q*4+2][lrow] = k4[q].z; KS[lseg+q*4+3][lrow] = k4[q].w;
        }
        const float4* vs = (const float4*)(Vg + (size_t)(q0+lrow)*64 + lseg);
        float4* vd = (float4*)(&Vs[lrow][lseg]);
        #pragma unroll
        for (int q = 0; q < 4; ++q) vd[q] = vs[q];
    }
    __syncthreads();

    const float invsc = 0.125f;
    float s[4][4];
    #pragma unroll
    for (int i = 0; i < 4; ++i)
        #pragma unroll
        for (int j = 0; j < 4; ++j) s[i][j] = 0.f;

    #pragma unroll 8
    for (int k = 0; k < 64; ++k) {
        float4 kv = *(const float4*)(&KS[k][tx*4]);
        float qv[4];
        #pragma unroll
        for (int i = 0; i < 4; ++i) qv[i] = Qs[ty*4+i][k];
        #pragma unroll
        for (int i = 0; i < 4; ++i) {
            s[i][0] = fmaf(qv[i], kv.x, s[i][0]); s[i][1] = fmaf(qv[i], kv.y, s[i][1]);
            s[i][2] = fmaf(qv[i], kv.z, s[i][2]); s[i][3] = fmaf(qv[i], kv.w, s[i][3]);
        }
    }
    #pragma unroll
    for (int i = 0; i < 4; ++i) {
        const int ii = ty*4 + i;
        #pragma unroll
        for (int j = 0; j < 4; ++j) {
            const int jj = tx*4 + j;
            s[i][j] = (jj >= ii) ? s[i][j] * invsc * dec[jj-ii] : 0.f;
        }
    }
    __syncthreads();
    #pragma unroll
    for (int i = 0; i < 4; ++i)
        *(float4*)(&KS[ty*4+i][tx*4]) = make_float4(s[i][0], s[i][1], s[i][2], s[i][3]);
    __syncthreads();

    float o[4][4];
    #pragma unroll
    for (int i = 0; i < 4; ++i)
        #pragma unroll
        for (int j = 0; j < 4; ++j) o[i][j] = 0.f;

    #pragma unroll 8
    for (int k = 0; k < 64; ++k) {
        float4 vv = *(const float4*)(&Vs[k][tx*4]);
        float sv[4];
        #pragma unroll
        for (int i = 0; i < 4; ++i) sv[i] = KS[ty*4+i][k];
        #pragma unroll
        for (int i = 0; i < 4; ++i) {
            o[i][0] = fmaf(sv[i], vv.x, o[i][0]); o[i][1] = fmaf(sv[i], vv.y, o[i][1]);
            o[i][2] = fmaf(sv[i], vv.z, o[i][2]); o[i][3] = fmaf(sv[i], vv.w, o[i][3]);
        }
    }

    float cr[4][4];
    #pragma unroll
    for (int i = 0; i < 4; ++i)
        #pragma unroll
        for (int j = 0; j < 4; ++j) cr[i][j] = 0.f;
    #pragma unroll 4
    for (int d = 0; d < 64; ++d) {
        const float4 rv = __ldg((const float4*)&Rg[d*64 + tx*4]);
        float qd[4];
        #pragma unroll
        for (int i = 0; i < 4; ++i) qd[i] = Qs[ty*4+i][d];
        #pragma unroll
        for (int i = 0; i < 4; ++i) {
            cr[i][0] = fmaf(qd[i], rv.x, cr[i][0]); cr[i][1] = fmaf(qd[i], rv.y, cr[i][1]);
            cr[i][2] = fmaf(qd[i], rv.z, cr[i][2]); cr[i][3] = fmaf(qd[i], rv.w, cr[i][3]);
        }
    }
    float lsum = 0.f, lsq = 0.f;
    #pragma unroll
    for (int i = 0; i < 4; ++i) {
        const int ii = ty*4 + i;
        const float coef = invsc * dec[64 - ii];
        #pragma unroll
        for (int j = 0; j < 4; ++j) {
            o[i][j] = fmaf(coef, cr[i][j], o[i][j]);
            lsum += o[i][j];
            lsq = fmaf(o[i][j], o[i][j], lsq);
        }
    }
    #pragma unroll
    for (int i = 0; i < 4; ++i) {
        const int t = q0 + ty*4 + i;
        float* dst = g_O + ((size_t)(b*T_ + t)) * E_ + h*64 + tx*4;
        *(float4*)dst = make_float4(o[i][0], o[i][1], o[i][2], o[i][3]);
    }
    #pragma unroll
    for (int off = 16; off > 0; off >>= 1) {
        lsum += __shfl_xor_sync(0xFFFFFFFF, lsum, off);
        lsq  += __shfl_xor_sync(0xFFFFFFFF, lsq,  off);
    }
    if ((tid & 31) == 0) {
        atomicAdd(&g_stat[bh].x, lsum);
        atomicAdd(&g_stat[bh].y, lsq);
    }
}

// ---------------- launch ----------------
extern "C" void kernel_launch(void* const* d_in, const int* in_sizes, int n_in,
                              void* d_out, int out_size)
{
    const float* x    = (const float*)d_in[0];
    const float* Wq   = (const float*)d_in[1];
    const float* bq   = (const float*)d_in[2];
    const float* Wk   = (const float*)d_in[3];
    const float* bk   = (const float*)d_in[4];
    const float* Wv   = (const float*)d_in[5];
    const float* bv   = (const float*)d_in[6];
    const float* Wg   = (const float*)d_in[7];
    const float* bg   = (const float*)d_in[8];
    const float* Wo   = (const float*)d_in[9];
    const float* bo   = (const float*)d_in[10];
    const float* gn_w = (const float*)d_in[11];
    const float* gn_b = (const float*)d_in[12];

    __nv_bfloat16 *Ah, *Al;
    cudaGetSymbolAddress((void**)&Ah, g_Ah);
    cudaGetSymbolAddress((void**)&Al, g_Al);

    cudaFuncSetAttribute(tc_gemm<0>, cudaFuncAttributeMaxDynamicSharedMemorySize, DYN_SMEM);
    cudaFuncSetAttribute(tc_gemm<1>, cudaFuncAttributeMaxDynamicSharedMemorySize, DYN_SMEM);

    const int ntot = M_*E_ + 5*E_*E_;
    split_all_kernel<<<(ntot + 255)/256, 256>>>(x, Wq, Wk, Wv, Wg, Wo);

    tc_gemm<0><<<dim3(E_/128, M_/128, 4), 256, DYN_SMEM>>>(Ah, Al, bq, bk, bv, bg, nullptr);

    ret_u_kernel<<<dim3(NT_-1, B_*H_), 256>>>();
    ret_scan_kernel<<<256, 256>>>();
    ret_attn_kernel<<<dim3(NT_, B_*H_), 256>>>();

    // Wo GEMM with fused GroupNorm-apply + gate in the A loader (gn_w, gn_b via b1, b2)
    tc_gemm<1><<<dim3(E_/128, M_/128, 1), 256, DYN_SMEM>>>(Ah, Al, bo, gn_w, gn_b, nullptr,
                                                           (float*)d_out);
}

// round 17
// speedup vs baseline: 1.0307x; 1.0307x over previous
#include <cuda_runtime.h>
#include <cuda_bf16.h>
#include <math.h>
#include <stdint.h>

#define B_  2
#define T_  2048
#define E_  1024
#define H_  16
#define HD_ 64
#define M_  (B_*T_)
#define NT_ (T_/64)

#define TSTRIDE 80
#define TILE_BYTES (128*TSTRIDE)
#define BUF_BYTES (4*TILE_BYTES)     // 40960
#define DYN_SMEM (2*BUF_BYTES)       // 81920 -> 2 CTAs/SM

// ---------------- scratch ----------------
__device__ float g_Q[B_*H_*T_*HD_];
__device__ float g_K[B_*H_*T_*HD_];
__device__ float g_V[B_*H_*T_*HD_];
__device__ float g_G[B_*T_*E_];
__device__ float g_O[B_*T_*E_];
__device__ float g_decay[H_*T_];
__device__ float g_R[B_*H_*NT_*HD_*HD_];
__device__ float g_U[B_*H_*NT_*HD_*HD_];
__device__ float4 g_rope[T_*32];
__device__ float2 g_stat[B_*H_];
__device__ __nv_bfloat16 g_Ah[M_*E_], g_Al[M_*E_];
__device__ __nv_bfloat16 g_Wh[5*E_*E_], g_Wl[5*E_*E_];

// ---------------- helpers ----------------
__device__ __forceinline__ uint32_t smem_u32(const void* p){
    uint32_t a; asm("{ .reg .u64 t; cvta.to.shared.u64 t, %1; cvt.u32.u64 %0, t; }":"=r"(a):"l"(p)); return a;
}
__device__ __forceinline__ void ldsm4(uint32_t r[4], uint32_t a){
    asm volatile("ldmatrix.sync.aligned.m8n8.x4.shared.b16 {%0,%1,%2,%3}, [%4];"
        :"=r"(r[0]),"=r"(r[1]),"=r"(r[2]),"=r"(r[3]):"r"(a));
}
__device__ __forceinline__ void mma16816(float c[4], const uint32_t a[4], const uint32_t b[2]){
    asm volatile("mma.sync.aligned.m16n8k16.row.col.f32.bf16.bf16.f32 "
        "{%0,%1,%2,%3}, {%4,%5,%6,%7}, {%8,%9}, {%0,%1,%2,%3};"
        : "+f"(c[0]),"+f"(c[1]),"+f"(c[2]),"+f"(c[3])
        : "r"(a[0]),"r"(a[1]),"r"(a[2]),"r"(a[3]),"r"(b[0]),"r"(b[1]));
}
#define CPA16(dst, src)  asm volatile("cp.async.cg.shared.global [%0], [%1], 16;"::"r"(dst),"l"(src))
#define CPA_COMMIT()     asm volatile("cp.async.commit_group;":::"memory")
#define CPA_WAIT1()      asm volatile("cp.async.wait_group 1;":::"memory")
#define CPA_WAIT0()      asm volatile("cp.async.wait_group 0;":::"memory")

// ---------------- prep: split + decay/rope tables + stat zero, one launch ----------------
__global__ void split_all_kernel(const float* __restrict__ x,
    const float* __restrict__ Wq, const float* __restrict__ Wk,
    const float* __restrict__ Wv, const float* __restrict__ Wg,
    const float* __restrict__ Wo)
{
    const int i = blockIdx.x*256 + threadIdx.x;
    if (i < B_*H_) g_stat[i] = make_float2(0.f, 0.f);
    if (i < H_*T_) {
        const int h = i >> 11, d = i & 2047;
        const double gamma = 1.0 - exp2(-(double)(5 + h));
        g_decay[i] = (float)pow(gamma, (double)d);
    }
    if (i < T_*32) {
        const int t = i >> 5, p = i & 31;
        float inv0 = (float)pow(10000.0, -(double)((2*p)   & 31) / 32.0);
        float inv1 = (float)pow(10000.0, -(double)((2*p+1) & 31) / 32.0);
        float s0,c0,s1,c1;
        sincosf((float)t * inv0, &s0, &c0);
        sincosf((float)t * inv1, &s1, &c1);
        g_rope[i] = make_float4(c0, s0, c1, s1);
    }
    const int NX = M_*E_;
    const int NTOT = NX + 5*E_*E_;
    if (i >= NTOT) return;
    float v; __nv_bfloat16 *hi, *lo;
    if (i < NX) {
        v = x[i]; hi = g_Ah + i; lo = g_Al + i;
    } else {
        const int j = i - NX;
        const int w = j >> 20, off = j & ((1<<20)-1);
        const float* src = (w==0)?Wq:(w==1)?Wk:(w==2)?Wv:(w==3)?Wg:Wo;
        v = src[off]; hi = g_Wh + j; lo = g_Wl + j;
    }
    const __nv_bfloat16 h = __float2bfloat16(v);
    *hi = h; *lo = __float2bfloat16(v - __bfloat162float(h));
}

// ---------------- HMMA GEMM 128x128 tile, bf16 3-term split, 2 CTAs/SM (R12 version) ----------------
__global__ __launch_bounds__(256, 2) void tc_gemm(
    const __nv_bfloat16* __restrict__ Ah, const __nv_bfloat16* __restrict__ Al,
    const float* __restrict__ b0, const float* __restrict__ b1,
    const float* __restrict__ b2, const float* __restrict__ b3,
    float* __restrict__ Cout, int single_mode)
{
    extern __shared__ __align__(16) char smem[];
    const int z = (single_mode >= 0) ? 4 : blockIdx.z;
    const float* bias = (z==1) ? b1 : (z==2) ? b2 : (z==3) ? b3 : b0;
    const __nv_bfloat16* Wh = g_Wh + (size_t)z * (E_*E_);
    const __nv_bfloat16* Wl = g_Wl + (size_t)z * (E_*E_);
    const int bm = blockIdx.y * 128, bn = blockIdx.x * 128;
    const int tid = threadIdx.x, wid = tid >> 5, lane = tid & 31;
    const int warp_m = wid >> 2, warp_n = wid & 3;
    const uint32_t sbase = smem_u32(smem);

    float c[4][4][4];
    #pragma unroll
    for (int i = 0; i < 4; ++i)
        #pragma unroll
        for (int j = 0; j < 4; ++j)
            #pragma unroll
            for (int r = 0; r < 4; ++r) c[i][j][r] = 0.f;

    const char* srcp[8];
    uint32_t dsto[8];
    #pragma unroll
    for (int q = 0; q < 8; ++q) {
        const int ch = tid + q*256;
        const int tile = ch >> 9, row = (ch & 511) >> 2, seg = (ch & 3) * 16;
        const __nv_bfloat16* base = (tile==0)?Ah:(tile==1)?Al:(tile==2)?Wh:Wl;
        const int rowbase = (tile < 2) ? bm : bn;
        srcp[q] = (const char*)(base + (size_t)(rowbase + row)*E_) + seg;
        dsto[q] = (uint32_t)(tile*TILE_BYTES + row*TSTRIDE + seg);
    }

    #define ISSUE(s) do { \
        const uint32_t dstbuf = sbase + (uint32_t)((s)&1)*BUF_BYTES; \
        const size_t soff = (size_t)(s)*64; \
        _Pragma("unroll") \
        for (int q = 0; q < 8; ++q) CPA16(dstbuf + dsto[q], srcp[q] + soff); \
        CPA_COMMIT(); \
    } while(0)

    ISSUE(0); ISSUE(1);
    const int lrow15 = lane & 15;
    const uint32_t kseg = (lane >> 4) * 16;

    uint32_t a_off[4], b_off[2];
    #pragma unroll
    for (int mf = 0; mf < 4; ++mf)
        a_off[mf] = (uint32_t)((warp_m*64 + mf*16 + lrow15) * TSTRIDE) + kseg;
    #pragma unroll
    for (int p = 0; p < 2; ++p)
        b_off[p] = (uint32_t)((warp_n*32 + p*16 + lrow15) * TSTRIDE) + kseg + 2*TILE_BYTES;

    for (int s = 0; s < 32; ++s) {
        if (s < 31) CPA_WAIT1(); else CPA_WAIT0();
        __syncthreads();
        const uint32_t buf = sbase + (uint32_t)(s & 1)*BUF_BYTES;

        uint32_t bh[2][4][2], bl[2][4][2];
        #pragma unroll
        for (int k16 = 0; k16 < 2; ++k16) {
            const uint32_t koff = buf + k16*32;
            #pragma unroll
            for (int p = 0; p < 2; ++p) {
                uint32_t r[4];
                ldsm4(r, koff + b_off[p]);
                bh[k16][2*p][0]=r[0]; bh[k16][2*p][1]=r[2];
                bh[k16][2*p+1][0]=r[1]; bh[k16][2*p+1][1]=r[3];
                ldsm4(r, koff + b_off[p] + TILE_BYTES);
                bl[k16][2*p][0]=r[0]; bl[k16][2*p][1]=r[2];
                bl[k16][2*p+1][0]=r[1]; bl[k16][2*p+1][1]=r[3];
            }
        }
        #pragma unroll
        for (int k16 = 0; k16 < 2; ++k16) {
            const uint32_t koff = buf + k16*32;
            #pragma unroll
            for (int mf = 0; mf < 4; ++mf) {
                uint32_t ah[4], al[4];
                ldsm4(ah, koff + a_off[mf]);
                ldsm4(al, koff + a_off[mf] + TILE_BYTES);
                #pragma unroll
                for (int nf = 0; nf < 4; ++nf) {
                    mma16816(c[mf][nf], ah, bh[k16][nf]);
                    mma16816(c[mf][nf], ah, bl[k16][nf]);
                    mma16816(c[mf][nf], al, bh[k16][nf]);
                }
            }
        }
        __syncthreads();
        if (s + 2 < 32) ISSUE(s + 2);
    }

    const int tq = lane >> 2, tr = lane & 3;
    #pragma unroll
    for (int mf = 0; mf < 4; ++mf) {
        #pragma unroll
        for (int nf = 0; nf < 4; ++nf) {
            #pragma unroll
            for (int half = 0; half < 2; ++half) {
                const int m = bm + warp_m*64 + mf*16 + tq + half*8;
                const int n0 = bn + warp_n*32 + nf*8 + tr*2;
                float v0 = c[mf][nf][half*2 + 0] + bias[n0];
                float v1 = c[mf][nf][half*2 + 1] + bias[n0 + 1];
                const int bb = m >> 11, t = m & 2047;
                if (z <= 2) {
                    const int h = n0 >> 6, hd = n0 & 63;
                    float* dst = ((z==0) ? g_Q : (z==1) ? g_K : g_V)
                                 + (((size_t)(bb*H_ + h) * T_ + t) * HD_) + hd;
                    if (z <= 1) {
                        const float4 cs = g_rope[(size_t)t*32 + (hd >> 1)];
                        *(float2*)dst = make_float2(v0*cs.x - v1*cs.y, v1*cs.z + v0*cs.w);
                    } else {
                        *(float2*)dst = make_float2(v0, v1);
                    }
                } else if (z == 3) {
                    g_G[(size_t)m*E_ + n0]     = v0 / (1.f + __expf(-v0));
                    g_G[(size_t)m*E_ + n0 + 1] = v1 / (1.f + __expf(-v1));
                } else {
                    *(float2*)(Cout + (size_t)m*E_ + n0) = make_float2(v0, v1);
                }
            }
        }
    }
    #undef ISSUE
}

// ---------------- Pass 1a: per-chunk outer products ----------------
__global__ __launch_bounds__(256) void ret_u_kernel()
{
    __shared__ float KT[64][64];
    __shared__ float Vs[64][64];

    const int cc = blockIdx.x + 1;
    const int bh = blockIdx.y, h = bh & 15;
    const int j0 = cc * 64;
    const float* dec = g_decay + h * T_;

    const float* Kg = g_K + (size_t)bh * T_ * HD_;
    const float* Vg = g_V + (size_t)bh * T_ * HD_;
    float* Ug = g_U + ((size_t)bh * NT_ + cc) * (HD_*HD_);

    const int tid = threadIdx.x;
    const int tx = tid & 15, ty = tid >> 4;
    const int lrow = tid >> 2, lseg = (tid & 3) * 16;

    {
        const float w = dec[lrow];
        float4 k4[4];
        const float4* ks = (const float4*)(Kg + (size_t)(j0+lrow)*64 + lseg);
        #pragma unroll
        for (int q = 0; q < 4; ++q) k4[q] = ks[q];
        #pragma unroll
        for (int q = 0; q < 4; ++q) {
            KT[lseg+q*4+0][lrow] = k4[q].x * w;
            KT[lseg+q*4+1][lrow] = k4[q].y * w;
            KT[lseg+q*4+2][lrow] = k4[q].z * w;
            KT[lseg+q*4+3][lrow] = k4[q].w * w;
        }
        const float4* vs = (const float4*)(Vg + (size_t)(j0+lrow)*64 + lseg);
        float4* vd = (float4*)(&Vs[lrow][lseg]);
        #pragma unroll
        for (int q = 0; q < 4; ++q) vd[q] = vs[q];
    }
    __syncthreads();

    float u[4][4];
    #pragma unroll
    for (int i = 0; i < 4; ++i)
        #pragma unroll
        for (int j = 0; j < 4; ++j) u[i][j] = 0.f;

    #pragma unroll 8
    for (int t = 0; t < 64; ++t) {
        float4 vv = *(const float4*)(&Vs[t][tx*4]);
        float kd[4];
        #pragma unroll
        for (int i = 0; i < 4; ++i) kd[i] = KT[ty*4+i][t];
        #pragma unroll
        for (int i = 0; i < 4; ++i) {
            u[i][0] = fmaf(kd[i], vv.x, u[i][0]); u[i][1] = fmaf(kd[i], vv.y, u[i][1]);
            u[i][2] = fmaf(kd[i], vv.z, u[i][2]); u[i][3] = fmaf(kd[i], vv.w, u[i][3]);
        }
    }
    #pragma unroll
    for (int i = 0; i < 4; ++i)
        *(float4*)&Ug[(ty*4+i)*64 + tx*4] = make_float4(u[i][0], u[i][1], u[i][2], u[i][3]);
}

// ---------------- Pass 1b: backward scan, all U loads hoisted (MLP=31) ----------------
__global__ __launch_bounds__(256) void ret_scan_kernel()
{
    const int idx = blockIdx.x*256 + threadIdx.x;       // 0..65535
    const int bh = idx >> 11;
    const int de = (idx & 2047) * 2;
    const float gL = g_decay[(bh & 15)*T_ + 64];

    float* Rg = g_R + (size_t)bh * NT_ * (HD_*HD_) + de;
    const float* Ug = g_U + (size_t)bh * NT_ * (HD_*HD_) + de;

    // independent loads issued back-to-back (high MLP), scan on registers
    float2 Uv[NT_-1];
    #pragma unroll
    for (int cc = 1; cc < NT_; ++cc)
        Uv[cc-1] = *(const float2*)(Ug + cc*(HD_*HD_));

    float2 R = make_float2(0.f, 0.f);
    *(float2*)(Rg + (NT_-1)*(HD_*HD_)) = R;
    #pragma unroll
    for (int cc = NT_-1; cc >= 1; --cc) {
        const float2 U = Uv[cc-1];
        R.x = U.x + gL*R.x; R.y = U.y + gL*R.y;
        *(float2*)(Rg + (cc-1)*(HD_*HD_)) = R;
    }
}

// ---------------- Pass 2: intra + cross chunk, fused GroupNorm stats ----------------
__global__ __launch_bounds__(256) void ret_attn_kernel()
{
    __shared__ float Qs[64][64];
    __shared__ float KS[64][64];
    __shared__ float Vs[64][64];

    const int bh = blockIdx.y, b = bh >> 4, h = bh & 15;
    const int cI = blockIdx.x, q0 = cI * 64;

    const float* Qg = g_Q + (size_t)bh * T_ * HD_;
    const float* Kg = g_K + (size_t)bh * T_ * HD_;
    const float* Vg = g_V + (size_t)bh * T_ * HD_;
    const float* dec = g_decay + h * T_;
    const float* Rg = g_R + ((size_t)bh * NT_ + cI) * (HD_*HD_);

    const int tid = threadIdx.x;
    const int tx = tid & 15, ty = tid >> 4;
    const int lrow = tid >> 2, lseg = (tid & 3) * 16;

    {
        const float4* qsrc = (const float4*)(Qg + (size_t)(q0+lrow)*64 + lseg);
        float4* qdst = (float4*)(&Qs[lrow][lseg]);
        #pragma unroll
        for (int q = 0; q < 4; ++q) qdst[q] = qsrc[q];
        float4 k4[4];
        const float4* ks = (const float4*)(Kg + (size_t)(q0+lrow)*64 + lseg);
        #pragma unroll
        for (int q = 0; q < 4; ++q) k4[q] = ks[q];
        #pragma unroll
        for (int q = 0; q < 4; ++q) {
            KS[lseg+q*4+0][lrow] = k4[q].x; KS[lseg+q*4+1][lrow] = k4[q].y;
            KS[lseg+q*4+2][lrow] = k4[q].z; KS[lseg+q*4+3][lrow] = k4[q].w;
        }
        const float4* vs = (const float4*)(Vg + (size_t)(q0+lrow)*64 + lseg);
        float4* vd = (float4*)(&Vs[lrow][lseg]);
        #pragma unroll
        for (int q = 0; q < 4; ++q) vd[q] = vs[q];
    }
    __syncthreads();

    const float invsc = 0.125f;
    float s[4][4];
    #pragma unroll
    for (int i = 0; i < 4; ++i)
        #pragma unroll
        for (int j = 0; j < 4; ++j) s[i][j] = 0.f;

    #pragma unroll 8
    for (int k = 0; k < 64; ++k) {
        float4 kv = *(const float4*)(&KS[k][tx*4]);
        float qv[4];
        #pragma unroll
        for (int i = 0; i < 4; ++i) qv[i] = Qs[ty*4+i][k];
        #pragma unroll
        for (int i = 0; i < 4; ++i) {
            s[i][0] = fmaf(qv[i], kv.x, s[i][0]); s[i][1] = fmaf(qv[i], kv.y, s[i][1]);
            s[i][2] = fmaf(qv[i], kv.z, s[i][2]); s[i][3] = fmaf(qv[i], kv.w, s[i][3]);
        }
    }
    #pragma unroll
    for (int i = 0; i < 4; ++i) {
        const int ii = ty*4 + i;
        #pragma unroll
        for (int j = 0; j < 4; ++j) {
            const int jj = tx*4 + j;
            s[i][j] = (jj >= ii) ? s[i][j] * invsc * dec[jj-ii] : 0.f;
        }
    }
    __syncthreads();
    #pragma unroll
    for (int i = 0; i < 4; ++i)
        *(float4*)(&KS[ty*4+i][tx*4]) = make_float4(s[i][0], s[i][1], s[i][2], s[i][3]);
    __syncthreads();

    float o[4][4];
    #pragma unroll
    for (int i = 0; i < 4; ++i)
        #pragma unroll
        for (int j = 0; j < 4; ++j) o[i][j] = 0.f;

    #pragma unroll 8
    for (int k = 0; k < 64; ++k) {
        float4 vv = *(const float4*)(&Vs[k][tx*4]);
        float sv[4];
        #pragma unroll
        for (int i = 0; i < 4; ++i) sv[i] = KS[ty*4+i][k];
        #pragma unroll
        for (int i = 0; i < 4; ++i) {
            o[i][0] = fmaf(sv[i], vv.x, o[i][0]); o[i][1] = fmaf(sv[i], vv.y, o[i][1]);
            o[i][2] = fmaf(sv[i], vv.z, o[i][2]); o[i][3] = fmaf(sv[i], vv.w, o[i][3]);
        }
    }

    float cr[4][4];
    #pragma unroll
    for (int i = 0; i < 4; ++i)
        #pragma unroll
        for (int j = 0; j < 4; ++j) cr[i][j] = 0.f;
    #pragma unroll 4
    for (int d = 0; d < 64; ++d) {
        const float4 rv = __ldg((const float4*)&Rg[d*64 + tx*4]);
        float qd[4];
        #pragma unroll
        for (int i = 0; i < 4; ++i) qd[i] = Qs[ty*4+i][d];
        #pragma unroll
        for (int i = 0; i < 4; ++i) {
            cr[i][0] = fmaf(qd[i], rv.x, cr[i][0]); cr[i][1] = fmaf(qd[i], rv.y, cr[i][1]);
            cr[i][2] = fmaf(qd[i], rv.z, cr[i][2]); cr[i][3] = fmaf(qd[i], rv.w, cr[i][3]);
        }
    }
    float lsum = 0.f, lsq = 0.f;
    #pragma unroll
    for (int i = 0; i < 4; ++i) {
        const int ii = ty*4 + i;
        const float coef = invsc * dec[64 - ii];
        #pragma unroll
        for (int j = 0; j < 4; ++j) {
            o[i][j] = fmaf(coef, cr[i][j], o[i][j]);
            lsum += o[i][j];
            lsq = fmaf(o[i][j], o[i][j], lsq);
        }
    }
    #pragma unroll
    for (int i = 0; i < 4; ++i) {
        const int t = q0 + ty*4 + i;
        float* dst = g_O + ((size_t)(b*T_ + t)) * E_ + h*64 + tx*4;
        *(float4*)dst = make_float4(o[i][0], o[i][1], o[i][2], o[i][3]);
    }
    #pragma unroll
    for (int off = 16; off > 0; off >>= 1) {
        lsum += __shfl_xor_sync(0xFFFFFFFF, lsum, off);
        lsq  += __shfl_xor_sync(0xFFFFFFFF, lsq,  off);
    }
    if ((tid & 31) == 0) {
        atomicAdd(&g_stat[bh].x, lsum);
        atomicAdd(&g_stat[bh].y, lsq);
    }
}

// ---------------- GroupNorm apply + gate -> bf16 split ----------------
__global__ __launch_bounds__(256) void gn_apply_kernel(
    const float* __restrict__ gn_w, const float* __restrict__ gn_b)
{
    const int i4 = blockIdx.x*256 + threadIdx.x;
    const size_t i = (size_t)i4 * 4;
    const int e0 = (int)(i & (E_-1));
    const int bt = (int)(i >> 10);
    const int bh = (bt >> 11) * H_ + (e0 >> 6);

    const float2 st = g_stat[bh];
    const float N = (float)(T_ * HD_);
    const float mu = st.x / N;
    const float rs = rsqrtf(st.y / N - mu*mu + 1e-5f);

    const float4 o = *(const float4*)(g_O + i);
    const float4 g = *(const float4*)(g_G + i);
    const float4 w = *(const float4*)(gn_w + e0);
    const float4 bb = *(const float4*)(gn_b + e0);

    float out[4];
    out[0] = ((o.x - mu) * rs * w.x + bb.x) * g.x;
    out[1] = ((o.y - mu) * rs * w.y + bb.y) * g.y;
    out[2] = ((o.z - mu) * rs * w.z + bb.z) * g.z;
    out[3] = ((o.w - mu) * rs * w.w + bb.w) * g.w;

    __nv_bfloat16 hi[4], lo[4];
    #pragma unroll
    for (int q = 0; q < 4; ++q) {
        hi[q] = __float2bfloat16(out[q]);
        lo[q] = __float2bfloat16(out[q] - __bfloat162float(hi[q]));
    }
    *(uint2*)(g_Ah + i) = *(uint2*)hi;
    *(uint2*)(g_Al + i) = *(uint2*)lo;
}

// ---------------- launch ----------------
extern "C" void kernel_launch(void* const* d_in, const int* in_sizes, int n_in,
                              void* d_out, int out_size)
{
    const float* x    = (const float*)d_in[0];
    const float* Wq   = (const float*)d_in[1];
    const float* bq   = (const float*)d_in[2];
    const float* Wk   = (const float*)d_in[3];
    const float* bk   = (const float*)d_in[4];
    const float* Wv   = (const float*)d_in[5];
    const float* bv   = (const float*)d_in[6];
    const float* Wg   = (const float*)d_in[7];
    const float* bg   = (const float*)d_in[8];
    const float* Wo   = (const float*)d_in[9];
    const float* bo   = (const float*)d_in[10];
    const float* gn_w = (const float*)d_in[11];
    const float* gn_b = (const float*)d_in[12];

    __nv_bfloat16 *Ah, *Al;
    cudaGetSymbolAddress((void**)&Ah, g_Ah);
    cudaGetSymbolAddress((void**)&Al, g_Al);

    cudaFuncSetAttribute(tc_gemm, cudaFuncAttributeMaxDynamicSharedMemorySize, DYN_SMEM);

    const int ntot = M_*E_ + 5*E_*E_;
    split_all_kernel<<<(ntot + 255)/256, 256>>>(x, Wq, Wk, Wv, Wg, Wo);

    tc_gemm<<<dim3(E_/128, M_/128, 4), 256, DYN_SMEM>>>(Ah, Al, bq, bk, bv, bg, nullptr, -1);

    ret_u_kernel<<<dim3(NT_-1, B_*H_), 256>>>();
    ret_scan_kernel<<<256, 256>>>();
    ret_attn_kernel<<<dim3(NT_, B_*H_), 256>>>();

    gn_apply_kernel<<<(M_*E_/4 + 255)/256, 256>>>(gn_w, gn_b);

    tc_gemm<<<dim3(E_/128, M_/128, 1), 256, DYN_SMEM>>>(Ah, Al, bo, nullptr, nullptr, nullptr,
                                                        (float*)d_out, 4);
}